// round 3
// baseline (speedup 1.0000x reference)
#include <cuda_runtime.h>
#include <stdint.h>

#define NN 100000
#define NE 1600000
#define NF 256
#define NH 64
#define NHTOT (NN * NH)          // 6,400,000

typedef unsigned long long ull;

// Scratch (static device globals — zero-initialized at load; each call restores
// the zero state itself so graph replays are deterministic).
__device__ __align__(16) float g_support[NHTOT];   // x @ W
__device__ __align__(16) float g_agg[NHTOT];       // segment_sum (bias cancels in BN)
__device__ double g_sum[NH];
__device__ double g_sumsq[NH];
__device__ float g_scale[NH];
__device__ float g_shift[NH];

// ---------------------------------------------------------------------------
// GEMM: support[NN,64] = x[NN,256] @ W[256,64]
// Block tile 128x64, 128 threads, 8x8 micro-tile, K-step 16, packed f32x2 FMA.
// Accumulators paired along M: acc2[i2][j] = (row 2*i2, row 2*i2+1) for col j.
// B is stored duplicated in shared so the (b_j, b_j) operand is a plain load.
// ---------------------------------------------------------------------------
__global__ __launch_bounds__(128) void k_gemm(const float* __restrict__ x,
                                              const float* __restrict__ W) {
    __shared__ float As[16][132];       // [k][row], row stride 528B = 16B-aligned
    __shared__ float Bd[16][128];       // [k][2*col] duplicated pairs

    const int tid = threadIdx.x;
    const int tx = tid & 7;     // output cols tx*8 .. tx*8+7
    const int ty = tid >> 3;    // output rows ty*8 .. ty*8+7
    const int rowBase = blockIdx.x * 128;

    ull acc2[4][8];
#pragma unroll
    for (int i = 0; i < 4; i++)
#pragma unroll
        for (int j = 0; j < 8; j++) acc2[i][j] = 0ull;

    for (int k0 = 0; k0 < NF; k0 += 16) {
        // A tile: 128 rows x 16 k
#pragma unroll
        for (int i = 0; i < 4; i++) {
            int idx = i * 512 + tid * 4;
            int r = idx >> 4;
            int kk = idx & 15;
            float4 v = make_float4(0.f, 0.f, 0.f, 0.f);
            int gr = rowBase + r;
            if (gr < NN)
                v = *reinterpret_cast<const float4*>(x + gr * NF + k0 + kk);
            As[kk + 0][r] = v.x;
            As[kk + 1][r] = v.y;
            As[kk + 2][r] = v.z;
            As[kk + 3][r] = v.w;
        }
        // B tile (duplicated): 16 k x 64 cols -> 128 packed
#pragma unroll
        for (int i = 0; i < 2; i++) {
            int idx = i * 512 + tid * 4;
            int kk = idx >> 6;
            int c = idx & 63;
            float4 v = *reinterpret_cast<const float4*>(W + (k0 + kk) * NH + c);
            *reinterpret_cast<float4*>(&Bd[kk][2 * c])     = make_float4(v.x, v.x, v.y, v.y);
            *reinterpret_cast<float4*>(&Bd[kk][2 * c + 4]) = make_float4(v.z, v.z, v.w, v.w);
        }
        __syncthreads();

#pragma unroll
        for (int kk = 0; kk < 16; kk++) {
            ulonglong2 A0 = *reinterpret_cast<const ulonglong2*>(&As[kk][ty * 8]);
            ulonglong2 A1 = *reinterpret_cast<const ulonglong2*>(&As[kk][ty * 8 + 4]);
            ull a2[4] = {A0.x, A0.y, A1.x, A1.y};
            ull b2[8];
#pragma unroll
            for (int m = 0; m < 4; m++) {
                ulonglong2 B = *reinterpret_cast<const ulonglong2*>(&Bd[kk][tx * 16 + m * 4]);
                b2[2 * m] = B.x;
                b2[2 * m + 1] = B.y;
            }
#pragma unroll
            for (int i = 0; i < 4; i++)
#pragma unroll
                for (int j = 0; j < 8; j++)
                    asm("fma.rn.f32x2 %0, %1, %2, %0;"
                        : "+l"(acc2[i][j]) : "l"(a2[i]), "l"(b2[j]));
        }
        __syncthreads();
    }

    // Unpack and store
#pragma unroll
    for (int i = 0; i < 4; i++) {
        float lo[8], hi[8];
#pragma unroll
        for (int j = 0; j < 8; j++) {
            float2 p = *reinterpret_cast<float2*>(&acc2[i][j]);
            lo[j] = p.x;
            hi[j] = p.y;
        }
        int gr0 = rowBase + ty * 8 + 2 * i;
        if (gr0 < NN) {
            *reinterpret_cast<float4*>(g_support + gr0 * NH + tx * 8) =
                make_float4(lo[0], lo[1], lo[2], lo[3]);
            *reinterpret_cast<float4*>(g_support + gr0 * NH + tx * 8 + 4) =
                make_float4(lo[4], lo[5], lo[6], lo[7]);
        }
        if (gr0 + 1 < NN) {
            *reinterpret_cast<float4*>(g_support + (gr0 + 1) * NH + tx * 8) =
                make_float4(hi[0], hi[1], hi[2], hi[3]);
            *reinterpret_cast<float4*>(g_support + (gr0 + 1) * NH + tx * 8 + 4) =
                make_float4(hi[4], hi[5], hi[6], hi[7]);
        }
    }
}

// ---------------------------------------------------------------------------
// Scatter: agg[row[e]] += ew[e] * support[col[e]]   (16 threads/edge, v4 red)
// ---------------------------------------------------------------------------
__global__ void k_scatter(const int* __restrict__ row, const int* __restrict__ col,
                          const float* __restrict__ ew) {
    int t = blockIdx.x * blockDim.x + threadIdx.x;
    int e = t >> 4;
    if (e >= NE) return;
    int l = t & 15;
    int c = __ldg(col + e);
    int r = __ldg(row + e);
    float w = __ldg(ew + e);
    float4 v = __ldg(reinterpret_cast<const float4*>(g_support) + c * 16 + l);
    float* dst = g_agg + r * 64 + l * 4;
    asm volatile("red.global.add.v4.f32 [%0], {%1, %2, %3, %4};"
                 :: "l"(dst), "f"(v.x * w), "f"(v.y * w), "f"(v.z * w), "f"(v.w * w)
                 : "memory");
}

// ---------------------------------------------------------------------------
// BN column stats: vectorized float4, 16 rows / block-iter, high MLP
// ---------------------------------------------------------------------------
__global__ __launch_bounds__(256) void k_colstats() {
    int j4 = threadIdx.x & 15;    // which float4 within the 64-col row
    int grp = threadIdx.x >> 4;   // 0..15: row group
    float4 s = make_float4(0.f, 0.f, 0.f, 0.f);
    float4 q = make_float4(0.f, 0.f, 0.f, 0.f);
    for (int r = blockIdx.x * 16 + grp; r < NN; r += gridDim.x * 16) {
        float4 v = *reinterpret_cast<const float4*>(g_agg + r * 64 + j4 * 4);
        s.x += v.x; s.y += v.y; s.z += v.z; s.w += v.w;
        q.x = fmaf(v.x, v.x, q.x); q.y = fmaf(v.y, v.y, q.y);
        q.z = fmaf(v.z, v.z, q.z); q.w = fmaf(v.w, v.w, q.w);
    }
    __shared__ float ss[16][68], sq[16][68];
    *reinterpret_cast<float4*>(&ss[grp][j4 * 4]) = s;
    *reinterpret_cast<float4*>(&sq[grp][j4 * 4]) = q;
    __syncthreads();
    if (threadIdx.x < 64) {
        int j = threadIdx.x;
        float S = 0.f, Q = 0.f;
#pragma unroll
        for (int g = 0; g < 16; g++) { S += ss[g][j]; Q += sq[g][j]; }
        atomicAdd(&g_sum[j], (double)S);
        atomicAdd(&g_sumsq[j], (double)Q);
    }
}

__global__ void k_finalize(const float* __restrict__ gamma, const float* __restrict__ beta) {
    int j = threadIdx.x;
    if (j < NH) {
        double mean = g_sum[j] / (double)NN;
        double var = g_sumsq[j] / (double)NN - mean * mean;
        float sc = (float)((double)gamma[j] * rsqrt(var + 1e-5));
        g_scale[j] = sc;
        g_shift[j] = beta[j] - (float)mean * sc;
        // restore zero state for the next (graph-replayed) call
        g_sum[j] = 0.0;
        g_sumsq[j] = 0.0;
    }
}

// ---------------------------------------------------------------------------
// Epilogue: BN affine + ReLU + JAX threefry dropout (partitionable layout);
// also re-zeroes g_agg for the next call.
// ---------------------------------------------------------------------------
#define TF_R(r) { x0 += x1; x1 = __funnelshift_l(x1, x1, (r)); x1 ^= x0; }

__device__ __forceinline__ uint32_t tf_bits(uint32_t i) {
    const uint32_t ks0 = 0u, ks1 = 42u, ks2 = 0x1BD11BDAu ^ 42u;
    uint32_t x0 = ks0;        // counts_hi (=0) + ks0
    uint32_t x1 = i + ks1;    // counts_lo (=i) + ks1
    TF_R(13) TF_R(15) TF_R(26) TF_R(6)
    x0 += ks1; x1 += ks2 + 1u;
    TF_R(17) TF_R(29) TF_R(16) TF_R(24)
    x0 += ks2; x1 += ks0 + 2u;
    TF_R(13) TF_R(15) TF_R(26) TF_R(6)
    x0 += ks0; x1 += ks1 + 3u;
    TF_R(17) TF_R(29) TF_R(16) TF_R(24)
    x0 += ks1; x1 += ks2 + 4u;
    TF_R(13) TF_R(15) TF_R(26) TF_R(6)
    x0 += ks2; x1 += ks0 + 5u;
    return x0 ^ x1;
}

__global__ void k_out(float* __restrict__ out) {
    int base = (blockIdx.x * blockDim.x + threadIdx.x) * 4;
    if (base >= NHTOT) return;
    float4 v4 = *reinterpret_cast<const float4*>(g_agg + base);
    // restore zero state for the next call's scatter accumulation
    *reinterpret_cast<float4*>(g_agg + base) = make_float4(0.f, 0.f, 0.f, 0.f);
    int j = base & 63;
    float vals[4] = {v4.x, v4.y, v4.z, v4.w};
    float res[4];
    const float inv_keep = 1.0f / 0.7f;
#pragma unroll
    for (int t = 0; t < 4; t++) {
        uint32_t bits = tf_bits((uint32_t)(base + t));
        float u = __uint_as_float((bits >> 9) | 0x3f800000u) - 1.0f;
        float v = fmaf(vals[t], g_scale[j + t], g_shift[j + t]);
        v = fmaxf(v, 0.0f);
        res[t] = (u < 0.7f) ? v * inv_keep : 0.0f;
    }
    *reinterpret_cast<float4*>(out + base) =
        make_float4(res[0], res[1], res[2], res[3]);
}

// ---------------------------------------------------------------------------
extern "C" void kernel_launch(void* const* d_in, const int* in_sizes, int n_in,
                              void* d_out, int out_size) {
    const float* x     = (const float*)d_in[0];
    const int*   row   = (const int*)d_in[1];
    const int*   col   = (const int*)d_in[2];
    const float* ew    = (const float*)d_in[3];
    const float* W     = (const float*)d_in[4];
    const float* gamma = (const float*)d_in[6];
    const float* beta  = (const float*)d_in[7];
    float* out = (float*)d_out;

    k_gemm<<<(NN + 127) / 128, 128>>>(x, W);
    k_scatter<<<(NE * 16) / 256, 256>>>(row, col, ew);
    k_colstats<<<1184, 256>>>();
    k_finalize<<<1, 64>>>(gamma, beta);
    k_out<<<(NHTOT / 4 + 255) / 256, 256>>>(out);
}

// round 4
// speedup vs baseline: 1.6143x; 1.6143x over previous
#include <cuda_runtime.h>
#include <stdint.h>

#define NN 100000
#define NE 1600000
#define NF 256
#define NH 64
#define NHTOT (NN * NH)          // 6,400,000

// Scratch (static device globals — zero-initialized at load; each call restores
// the zero state itself so graph replays are deterministic).
__device__ __align__(16) float g_support[NHTOT];   // x @ W
__device__ __align__(16) float g_agg[NHTOT];       // segment_sum (bias cancels in BN)
__device__ double g_sum[NH];
__device__ double g_sumsq[NH];
__device__ float g_scale[NH];
__device__ float g_shift[NH];
__device__ unsigned int g_arrive;                  // colstats completion counter

// ---------------------------------------------------------------------------
// GEMM: support[NN,64] = x[NN,256] @ W[256,64]
// Block tile 128x64, 128 threads, 8x8 micro-tile, K-step 16 (scalar FFMA; the
// f32x2 packed variant measured 2.5x SLOWER in R3 — do not reintroduce without
// SASS evidence).
// ---------------------------------------------------------------------------
__global__ __launch_bounds__(128) void k_gemm(const float* __restrict__ x,
                                              const float* __restrict__ W) {
    __shared__ float As[16][132];   // [k][row]
    __shared__ float Bs[16][64];    // [k][col]

    const int tid = threadIdx.x;
    const int tx = tid & 7;     // output cols tx*8 .. tx*8+7
    const int ty = tid >> 3;    // output rows ty*8 .. ty*8+7
    const int rowBase = blockIdx.x * 128;

    float acc[8][8];
#pragma unroll
    for (int i = 0; i < 8; i++)
#pragma unroll
        for (int j = 0; j < 8; j++) acc[i][j] = 0.0f;

    for (int k0 = 0; k0 < NF; k0 += 16) {
#pragma unroll
        for (int i = 0; i < 4; i++) {
            int idx = i * 512 + tid * 4;
            int r = idx >> 4;
            int kk = idx & 15;
            float4 v = make_float4(0.f, 0.f, 0.f, 0.f);
            int gr = rowBase + r;
            if (gr < NN)
                v = *reinterpret_cast<const float4*>(x + gr * NF + k0 + kk);
            As[kk + 0][r] = v.x;
            As[kk + 1][r] = v.y;
            As[kk + 2][r] = v.z;
            As[kk + 3][r] = v.w;
        }
#pragma unroll
        for (int i = 0; i < 2; i++) {
            int idx = i * 512 + tid * 4;
            int kk = idx >> 6;
            int c = idx & 63;
            *reinterpret_cast<float4*>(&Bs[kk][c]) =
                *reinterpret_cast<const float4*>(W + (k0 + kk) * NH + c);
        }
        __syncthreads();

#pragma unroll
        for (int kk = 0; kk < 16; kk++) {
            float a[8], bb[8];
            *reinterpret_cast<float4*>(&a[0]) = *reinterpret_cast<const float4*>(&As[kk][ty * 8]);
            *reinterpret_cast<float4*>(&a[4]) = *reinterpret_cast<const float4*>(&As[kk][ty * 8 + 4]);
            *reinterpret_cast<float4*>(&bb[0]) = *reinterpret_cast<const float4*>(&Bs[kk][tx * 8]);
            *reinterpret_cast<float4*>(&bb[4]) = *reinterpret_cast<const float4*>(&Bs[kk][tx * 8 + 4]);
#pragma unroll
            for (int i = 0; i < 8; i++)
#pragma unroll
                for (int j = 0; j < 8; j++) acc[i][j] = fmaf(a[i], bb[j], acc[i][j]);
        }
        __syncthreads();
    }

#pragma unroll
    for (int i = 0; i < 8; i++) {
        int gr = rowBase + ty * 8 + i;
        if (gr < NN) {
            *reinterpret_cast<float4*>(g_support + gr * NH + tx * 8) =
                make_float4(acc[i][0], acc[i][1], acc[i][2], acc[i][3]);
            *reinterpret_cast<float4*>(g_support + gr * NH + tx * 8 + 4) =
                make_float4(acc[i][4], acc[i][5], acc[i][6], acc[i][7]);
        }
    }
}

// ---------------------------------------------------------------------------
// Scatter: agg[row[e]] += ew[e] * support[col[e]]   (16 threads/edge, v4 red)
// ---------------------------------------------------------------------------
__global__ void k_scatter(const int* __restrict__ row, const int* __restrict__ col,
                          const float* __restrict__ ew) {
    int t = blockIdx.x * blockDim.x + threadIdx.x;
    int e = t >> 4;
    if (e >= NE) return;
    int l = t & 15;
    int c = __ldg(col + e);
    int r = __ldg(row + e);
    float w = __ldg(ew + e);
    float4 v = __ldg(reinterpret_cast<const float4*>(g_support) + c * 16 + l);
    float* dst = g_agg + r * 64 + l * 4;
    asm volatile("red.global.add.v4.f32 [%0], {%1, %2, %3, %4};"
                 :: "l"(dst), "f"(v.x * w), "f"(v.y * w), "f"(v.z * w), "f"(v.w * w)
                 : "memory");
}

// ---------------------------------------------------------------------------
// BN column stats (float4, high MLP) + fused finalize in the last block.
// ---------------------------------------------------------------------------
#define NSTAT_BLK 1184

__global__ __launch_bounds__(256) void k_colstats(const float* __restrict__ gamma,
                                                  const float* __restrict__ beta) {
    int j4 = threadIdx.x & 15;    // which float4 within the 64-col row
    int grp = threadIdx.x >> 4;   // 0..15: row group
    float4 s = make_float4(0.f, 0.f, 0.f, 0.f);
    float4 q = make_float4(0.f, 0.f, 0.f, 0.f);
    for (int r = blockIdx.x * 16 + grp; r < NN; r += NSTAT_BLK * 16) {
        float4 v = *reinterpret_cast<const float4*>(g_agg + r * 64 + j4 * 4);
        s.x += v.x; s.y += v.y; s.z += v.z; s.w += v.w;
        q.x = fmaf(v.x, v.x, q.x); q.y = fmaf(v.y, v.y, q.y);
        q.z = fmaf(v.z, v.z, q.z); q.w = fmaf(v.w, v.w, q.w);
    }
    __shared__ float ss[16][68], sq[16][68];
    __shared__ bool s_last;
    *reinterpret_cast<float4*>(&ss[grp][j4 * 4]) = s;
    *reinterpret_cast<float4*>(&sq[grp][j4 * 4]) = q;
    __syncthreads();
    if (threadIdx.x < 64) {
        int j = threadIdx.x;
        float S = 0.f, Q = 0.f;
#pragma unroll
        for (int g = 0; g < 16; g++) { S += ss[g][j]; Q += sq[g][j]; }
        atomicAdd(&g_sum[j], (double)S);
        atomicAdd(&g_sumsq[j], (double)Q);
    }
    __syncthreads();
    if (threadIdx.x == 0) {
        __threadfence();
        unsigned int prev = atomicAdd(&g_arrive, 1u);
        s_last = (prev == NSTAT_BLK - 1);
    }
    __syncthreads();
    if (s_last) {
        if (threadIdx.x < NH) {
            int j = threadIdx.x;
            double mean = g_sum[j] / (double)NN;
            double var = g_sumsq[j] / (double)NN - mean * mean;
            float sc = (float)((double)gamma[j] * rsqrt(var + 1e-5));
            g_scale[j] = sc;
            g_shift[j] = beta[j] - (float)mean * sc;
            // restore zero state for the next (graph-replayed) call
            g_sum[j] = 0.0;
            g_sumsq[j] = 0.0;
        }
        if (threadIdx.x == 64) g_arrive = 0u;
    }
}

// ---------------------------------------------------------------------------
// Epilogue: BN affine + ReLU + JAX threefry dropout (partitionable layout);
// also re-zeroes g_agg for the next call.
// ---------------------------------------------------------------------------
#define TF_R(r) { x0 += x1; x1 = __funnelshift_l(x1, x1, (r)); x1 ^= x0; }

__device__ __forceinline__ uint32_t tf_bits(uint32_t i) {
    const uint32_t ks0 = 0u, ks1 = 42u, ks2 = 0x1BD11BDAu ^ 42u;
    uint32_t x0 = ks0;        // counts_hi (=0) + ks0
    uint32_t x1 = i + ks1;    // counts_lo (=i) + ks1
    TF_R(13) TF_R(15) TF_R(26) TF_R(6)
    x0 += ks1; x1 += ks2 + 1u;
    TF_R(17) TF_R(29) TF_R(16) TF_R(24)
    x0 += ks2; x1 += ks0 + 2u;
    TF_R(13) TF_R(15) TF_R(26) TF_R(6)
    x0 += ks0; x1 += ks1 + 3u;
    TF_R(17) TF_R(29) TF_R(16) TF_R(24)
    x0 += ks1; x1 += ks2 + 4u;
    TF_R(13) TF_R(15) TF_R(26) TF_R(6)
    x0 += ks2; x1 += ks0 + 5u;
    return x0 ^ x1;
}

__global__ void k_out(float* __restrict__ out) {
    int base = (blockIdx.x * blockDim.x + threadIdx.x) * 4;
    if (base >= NHTOT) return;
    float4 v4 = *reinterpret_cast<const float4*>(g_agg + base);
    // restore zero state for the next call's scatter accumulation
    *reinterpret_cast<float4*>(g_agg + base) = make_float4(0.f, 0.f, 0.f, 0.f);
    int j = base & 63;
    float vals[4] = {v4.x, v4.y, v4.z, v4.w};
    float res[4];
    const float inv_keep = 1.0f / 0.7f;
#pragma unroll
    for (int t = 0; t < 4; t++) {
        uint32_t bits = tf_bits((uint32_t)(base + t));
        float u = __uint_as_float((bits >> 9) | 0x3f800000u) - 1.0f;
        float v = fmaf(vals[t], g_scale[j + t], g_shift[j + t]);
        v = fmaxf(v, 0.0f);
        res[t] = (u < 0.7f) ? v * inv_keep : 0.0f;
    }
    *reinterpret_cast<float4*>(out + base) =
        make_float4(res[0], res[1], res[2], res[3]);
}

// ---------------------------------------------------------------------------
extern "C" void kernel_launch(void* const* d_in, const int* in_sizes, int n_in,
                              void* d_out, int out_size) {
    const float* x     = (const float*)d_in[0];
    const int*   row   = (const int*)d_in[1];
    const int*   col   = (const int*)d_in[2];
    const float* ew    = (const float*)d_in[3];
    const float* W     = (const float*)d_in[4];
    const float* gamma = (const float*)d_in[6];
    const float* beta  = (const float*)d_in[7];
    float* out = (float*)d_out;

    k_gemm<<<(NN + 127) / 128, 128>>>(x, W);
    k_scatter<<<(NE * 16) / 256, 256>>>(row, col, ew);
    k_colstats<<<NSTAT_BLK, 256>>>(gamma, beta);
    k_out<<<(NHTOT / 4 + 255) / 256, 256>>>(out);
}